// round 1
// baseline (speedup 1.0000x reference)
#include <cuda_runtime.h>
#include <math.h>

// ---------------------------------------------------------------------------
// RobustAttentionBlock  (B=4, S=2048, E=1280, R=325, 3R=975)
//
// Math: Re(FFT) / Re(IFFT) along seq == GEMM with symmetric cosine matrix
//   C[k,n] = cos(2*pi*k*n/2048);  Re(IFFT(y)) = (1/2048) C @ y  (y real).
// Whole block = LayerNorm + GEMM chain + abs-softmax.
// ---------------------------------------------------------------------------

#define EDIM   1280
#define SEQ    2048
#define BATCH  4
#define RANKD  325
#define N3R    975
#define BSROWS (BATCH * SEQ)   // 8192

// ------------------------- scratch (device globals) ------------------------
// sizes in floats
#define SZ_XNORM  (8192LL * 1280)        // 10,485,760
#define SZ_QKV    (8192LL * 975)         //  7,987,200
#define SZ_T      (8192LL * 1280)        // 10,485,760 (q,k,v,qf,kf,vf)
#define SZ_SCORES (4LL * 2048 * 2048)    // 16,777,216
#define SZ_COS    (2048LL * 2048)        //  4,194,304

#define OFF_XNORM  0LL
#define OFF_QKV    (OFF_XNORM + SZ_XNORM)       // 10485760
#define OFF_Q      (OFF_QKV   + SZ_QKV)         // 18472960
#define OFF_K      (OFF_Q     + SZ_T)           // 28958720
#define OFF_V      (OFF_K     + SZ_T)           // 39444480
#define OFF_QF     (OFF_V     + SZ_T)           // 49930240
#define OFF_KF     (OFF_QF    + SZ_T)           // 60416000
#define OFF_VF     (OFF_KF    + SZ_T)           // 70901760
#define OFF_SCORES (OFF_VF    + SZ_T)           // 81387520
#define OFF_COS    (OFF_SCORES + SZ_SCORES)     // 98164736
#define TOTAL_F    (OFF_COS + SZ_COS)           // 102359040 floats (~410 MB)

__device__ float g_buf[TOTAL_F];

// ------------------------------ reductions ---------------------------------
__device__ __forceinline__ float warpReduceSum(float v) {
    #pragma unroll
    for (int o = 16; o > 0; o >>= 1) v += __shfl_xor_sync(0xffffffffu, v, o);
    return v;
}
__device__ __forceinline__ float warpReduceMax(float v) {
    #pragma unroll
    for (int o = 16; o > 0; o >>= 1) v = fmaxf(v, __shfl_xor_sync(0xffffffffu, v, o));
    return v;
}

// ------------------------------ layernorm ----------------------------------
__global__ __launch_bounds__(256) void layernorm_kernel(
    const float* __restrict__ x, const float* __restrict__ gamma,
    const float* __restrict__ beta, float* __restrict__ y)
{
    long long row = blockIdx.x;
    const float* xr = x + row * EDIM;
    float* yr = y + row * EDIM;

    float s = 0.f, s2 = 0.f;
    for (int i = threadIdx.x; i < EDIM; i += 256) {
        float v = xr[i];
        s += v; s2 += v * v;
    }
    __shared__ float sh[64];
    s  = warpReduceSum(s);
    s2 = warpReduceSum(s2);
    int w = threadIdx.x >> 5, l = threadIdx.x & 31;
    if (l == 0) { sh[w] = s; sh[32 + w] = s2; }
    __syncthreads();
    if (w == 0) {
        float a = (l < 8) ? sh[l] : 0.f;
        float b = (l < 8) ? sh[32 + l] : 0.f;
        a = warpReduceSum(a);
        b = warpReduceSum(b);
        if (l == 0) { sh[0] = a; sh[1] = b; }
    }
    __syncthreads();
    float mean = sh[0] * (1.0f / EDIM);
    float var  = sh[1] * (1.0f / EDIM) - mean * mean;
    float inv  = rsqrtf(var + 1e-5f);
    for (int i = threadIdx.x; i < EDIM; i += 256) {
        yr[i] = (xr[i] - mean) * inv * gamma[i] + beta[i];
    }
}

// ------------------------------ cosine fill --------------------------------
__global__ __launch_bounds__(256) void fill_cos_kernel(float* __restrict__ Cm)
{
    long long idx = (long long)blockIdx.x * 256 + threadIdx.x;
    if (idx >= SZ_COS) return;
    int kk = (int)(idx >> 11);
    int nn = (int)(idx & 2047);
    int m = (kk * nn) & 2047;  // (k*n) mod 2048 exact in int32
    Cm[idx] = cosf((float)m * 0.003067961575771282f);  // 2*pi/2048
}

// ------------------------------ abs-softmax --------------------------------
// one block per row of length 2048, in-place
__global__ __launch_bounds__(256) void softmax_abs_kernel(float* __restrict__ s)
{
    long long row = blockIdx.x;
    float* sr = s + row * (long long)SEQ;
    float vals[8];
    float mx = -1e30f;
    #pragma unroll
    for (int i = 0; i < 8; i++) {
        float v = fabsf(sr[threadIdx.x + i * 256]);
        vals[i] = v;
        mx = fmaxf(mx, v);
    }
    __shared__ float sh[32];
    mx = warpReduceMax(mx);
    int w = threadIdx.x >> 5, l = threadIdx.x & 31;
    if (l == 0) sh[w] = mx;
    __syncthreads();
    if (w == 0) {
        float a = (l < 8) ? sh[l] : -1e30f;
        a = warpReduceMax(a);
        if (l == 0) sh[0] = a;
    }
    __syncthreads();
    float M = sh[0];
    float sum = 0.f;
    #pragma unroll
    for (int i = 0; i < 8; i++) {
        vals[i] = expf(vals[i] - M);
        sum += vals[i];
    }
    __syncthreads();
    sum = warpReduceSum(sum);
    if (l == 0) sh[w] = sum;
    __syncthreads();
    if (w == 0) {
        float a = (l < 8) ? sh[l] : 0.f;
        a = warpReduceSum(a);
        if (l == 0) sh[0] = a;
    }
    __syncthreads();
    float inv = 1.0f / sh[0];
    #pragma unroll
    for (int i = 0; i < 8; i++) {
        sr[threadIdx.x + i * 256] = vals[i] * inv;
    }
}

// ------------------------------ SGEMM --------------------------------------
// C[M,N] = alpha * A @ op(B) (+ Res), batched via blockIdx.z with strides.
// 128x128 block tile, BK=8, 8x8 per thread, 256 threads, fully guarded.
template <bool TRANSB>
__global__ __launch_bounds__(256) void sgemm_kernel(
    const float* __restrict__ A, int lda, long long sA,
    const float* __restrict__ B, int ldb, long long sB,
    float* __restrict__ C, int ldc, long long sC,
    int M, int N, int K, float alpha,
    const float* __restrict__ Res, long long sRes)
{
    const int BM = 128, BN = 128, BK = 8, TM = 8, TN = 8;
    __shared__ float As[BK][BM];
    __shared__ float Bs[BK][BN];

    long long bz = blockIdx.z;
    A += bz * sA;
    B += bz * sB;
    C += bz * sC;
    if (Res) Res += bz * sRes;

    int row0 = blockIdx.y * BM;
    int col0 = blockIdx.x * BN;
    int tid = threadIdx.x;
    int tx = tid & 15, ty = tid >> 4;

    float acc[TM][TN];
    #pragma unroll
    for (int i = 0; i < TM; i++)
        #pragma unroll
        for (int j = 0; j < TN; j++) acc[i][j] = 0.f;

    for (int k0 = 0; k0 < K; k0 += BK) {
        // load A tile (BM x BK) -> As[k][m]
        #pragma unroll
        for (int i = 0; i < 4; i++) {
            int idx = tid + i * 256;
            int m = idx >> 3, kk = idx & 7;
            int gr = row0 + m, gk = k0 + kk;
            As[kk][m] = (gr < M && gk < K) ? A[(long long)gr * lda + gk] : 0.f;
        }
        // load B tile -> Bs[k][n]
        #pragma unroll
        for (int i = 0; i < 4; i++) {
            int idx = tid + i * 256;
            if (!TRANSB) {
                int kk = idx >> 7, n = idx & 127;
                int gk = k0 + kk, gc = col0 + n;
                Bs[kk][n] = (gk < K && gc < N) ? B[(long long)gk * ldb + gc] : 0.f;
            } else {
                int n = idx >> 3, kk = idx & 7;
                int gc = col0 + n, gk = k0 + kk;
                Bs[kk][n] = (gk < K && gc < N) ? B[(long long)gc * ldb + gk] : 0.f;
            }
        }
        __syncthreads();

        #pragma unroll
        for (int kk = 0; kk < BK; kk++) {
            float ra[TM], rb[TN];
            #pragma unroll
            for (int i = 0; i < TM; i++) ra[i] = As[kk][ty * TM + i];
            #pragma unroll
            for (int j = 0; j < TN; j++) rb[j] = Bs[kk][tx * TN + j];
            #pragma unroll
            for (int i = 0; i < TM; i++)
                #pragma unroll
                for (int j = 0; j < TN; j++)
                    acc[i][j] += ra[i] * rb[j];
        }
        __syncthreads();
    }

    #pragma unroll
    for (int i = 0; i < TM; i++) {
        int r = row0 + ty * TM + i;
        if (r >= M) continue;
        #pragma unroll
        for (int j = 0; j < TN; j++) {
            int c = col0 + tx * TN + j;
            if (c >= N) continue;
            float v = alpha * acc[i][j];
            if (Res) v += Res[(long long)r * ldc + c];
            C[(long long)r * ldc + c] = v;
        }
    }
}

// ------------------------------ host side ----------------------------------
static inline void run_gemm(bool transb,
                            const float* A, int lda, long long sA,
                            const float* B, int ldb, long long sB,
                            float* C, int ldc, long long sC,
                            int M, int N, int K, float alpha,
                            const float* Res, long long sRes, int nb)
{
    dim3 grid((N + 127) / 128, (M + 127) / 128, nb);
    if (transb)
        sgemm_kernel<true><<<grid, 256>>>(A, lda, sA, B, ldb, sB, C, ldc, sC,
                                          M, N, K, alpha, Res, sRes);
    else
        sgemm_kernel<false><<<grid, 256>>>(A, lda, sA, B, ldb, sB, C, ldc, sC,
                                           M, N, K, alpha, Res, sRes);
}

extern "C" void kernel_launch(void* const* d_in, const int* in_sizes, int n_in,
                              void* d_out, int out_size)
{
    const float* x     = (const float*)d_in[0];  // (4,2048,1280)
    const float* Wqkv  = (const float*)d_in[1];  // (1280,975)
    const float* Wq    = (const float*)d_in[2];  // (325,1280)
    const float* Wk    = (const float*)d_in[3];  // (325,1280)
    const float* Wv    = (const float*)d_in[4];  // (325,1280)
    const float* Wout  = (const float*)d_in[5];  // (1280,1280)
    const float* gamma = (const float*)d_in[6];  // (1280,)
    const float* beta  = (const float*)d_in[7];  // (1280,)
    float* out = (float*)d_out;                  // (4,2048,1280)

    float* buf = nullptr;
    cudaGetSymbolAddress((void**)&buf, g_buf);

    float* xn     = buf + OFF_XNORM;
    float* qkv    = buf + OFF_QKV;
    float* q      = buf + OFF_Q;
    float* k      = buf + OFF_K;
    float* v      = buf + OFF_V;
    float* qf     = buf + OFF_QF;
    float* kf     = buf + OFF_KF;
    float* vf     = buf + OFF_VF;
    float* scores = buf + OFF_SCORES;
    float* cosm   = buf + OFF_COS;

    const long long sT = (long long)SEQ * EDIM;   // per-batch stride of (2048,1280)
    const long long sS = (long long)SEQ * SEQ;    // per-batch stride of (2048,2048)
    const float scale = 0.07905694150420949f;     // 1/sqrt(160)

    // 1. LayerNorm
    layernorm_kernel<<<BSROWS, 256>>>(x, gamma, beta, xn);

    // 2. cosine DFT matrix
    fill_cos_kernel<<<(unsigned)((SZ_COS + 255) / 256), 256>>>(cosm);

    // 3. qkv = xn @ W_qkv   (8192 x 975)
    run_gemm(false, xn, EDIM, 0, Wqkv, N3R, 0, qkv, N3R, 0,
             BSROWS, N3R, EDIM, 1.f, nullptr, 0, 1);

    // 4. q/k/v = qkv[:, i*325:(i+1)*325] @ W_{q,k,v}   (8192 x 1280)
    run_gemm(false, qkv + 0 * RANKD, N3R, 0, Wq, EDIM, 0, q, EDIM, 0,
             BSROWS, EDIM, RANKD, 1.f, nullptr, 0, 1);
    run_gemm(false, qkv + 1 * RANKD, N3R, 0, Wk, EDIM, 0, k, EDIM, 0,
             BSROWS, EDIM, RANKD, 1.f, nullptr, 0, 1);
    run_gemm(false, qkv + 2 * RANKD, N3R, 0, Wv, EDIM, 0, v, EDIM, 0,
             BSROWS, EDIM, RANKD, 1.f, nullptr, 0, 1);

    // 5. FFT real part: tf = C @ t (per batch)
    run_gemm(false, cosm, SEQ, 0, q, EDIM, sT, qf, EDIM, sT,
             SEQ, EDIM, SEQ, 1.f, nullptr, 0, BATCH);
    run_gemm(false, cosm, SEQ, 0, k, EDIM, sT, kf, EDIM, sT,
             SEQ, EDIM, SEQ, 1.f, nullptr, 0, BATCH);
    run_gemm(false, cosm, SEQ, 0, v, EDIM, sT, vf, EDIM, sT,
             SEQ, EDIM, SEQ, 1.f, nullptr, 0, BATCH);

    // 6. scores = (qf @ kf^T) / sqrt(160)   (per batch 2048x2048)
    run_gemm(true, qf, EDIM, sT, kf, EDIM, sT, scores, SEQ, sS,
             SEQ, SEQ, EDIM, scale, nullptr, 0, BATCH);

    // 7. attn = softmax(|scores|) in-place
    softmax_abs_kernel<<<BATCH * SEQ, 256>>>(scores);

    // 8. out_fft = attn @ vf  -> reuse q
    run_gemm(false, scores, SEQ, sS, vf, EDIM, sT, q, EDIM, sT,
             SEQ, EDIM, SEQ, 1.f, nullptr, 0, BATCH);

    // 9. attn_out = (1/2048) * C @ out_fft -> reuse k
    run_gemm(false, cosm, SEQ, 0, q, EDIM, sT, k, EDIM, sT,
             SEQ, EDIM, SEQ, 1.f / 2048.f, nullptr, 0, BATCH);

    // 10. out = x + attn_out @ W_out
    run_gemm(false, k, EDIM, 0, Wout, EDIM, 0, out, EDIM, 0,
             BSROWS, EDIM, EDIM, 1.f, x, 0, 1);
}

// round 4
// speedup vs baseline: 1.8807x; 1.8807x over previous
#include <cuda_runtime.h>
#include <math.h>

// ---------------------------------------------------------------------------
// RobustAttentionBlock  (B=4, S=2048, E=1280, R=325, 3R=975)
//
// Re(FFT)/Re(IFFT) along seq via real radix-2 smem FFT (2 real columns packed
// per complex transform). cos is even => Re(IFFT(y)) = Re(FFT(y))/2048 for
// real y. GEMM chain: double-buffered fp32 SIMT SGEMM.
// ---------------------------------------------------------------------------

#define EDIM   1280
#define SEQ    2048
#define BATCH  4
#define RANKD  325
#define N3R    975
#define BSROWS (BATCH * SEQ)   // 8192

#define SZ_XNORM  (8192LL * 1280)
#define SZ_QKV    (8192LL * 975)
#define SZ_T      (8192LL * 1280)
#define SZ_SCORES (4LL * 2048 * 2048)
#define SZ_TW     (2048LL)

#define OFF_XNORM  0LL
#define OFF_QKV    (OFF_XNORM + SZ_XNORM)
#define OFF_Q      (OFF_QKV   + SZ_QKV)
#define OFF_K      (OFF_Q     + SZ_T)
#define OFF_V      (OFF_K     + SZ_T)
#define OFF_QF     (OFF_V     + SZ_T)
#define OFF_KF     (OFF_QF    + SZ_T)
#define OFF_VF     (OFF_KF    + SZ_T)
#define OFF_SCORES (OFF_VF    + SZ_T)
#define OFF_TW     (OFF_SCORES + SZ_SCORES)
#define TOTAL_F    (OFF_TW + SZ_TW)

__device__ float g_buf[TOTAL_F];

// ------------------------------ reductions ---------------------------------
__device__ __forceinline__ float warpReduceSum(float v) {
    #pragma unroll
    for (int o = 16; o > 0; o >>= 1) v += __shfl_xor_sync(0xffffffffu, v, o);
    return v;
}
__device__ __forceinline__ float warpReduceMax(float v) {
    #pragma unroll
    for (int o = 16; o > 0; o >>= 1) v = fmaxf(v, __shfl_xor_sync(0xffffffffu, v, o));
    return v;
}

// ------------------------------ layernorm ----------------------------------
__global__ __launch_bounds__(256) void layernorm_kernel(
    const float* __restrict__ x, const float* __restrict__ gamma,
    const float* __restrict__ beta, float* __restrict__ y)
{
    long long row = blockIdx.x;
    const float* xr = x + row * EDIM;
    float* yr = y + row * EDIM;

    float s = 0.f, s2 = 0.f;
    for (int i = threadIdx.x; i < EDIM; i += 256) {
        float v = xr[i];
        s += v; s2 += v * v;
    }
    __shared__ float sh[64];
    s  = warpReduceSum(s);
    s2 = warpReduceSum(s2);
    int w = threadIdx.x >> 5, l = threadIdx.x & 31;
    if (l == 0) { sh[w] = s; sh[32 + w] = s2; }
    __syncthreads();
    if (w == 0) {
        float a = (l < 8) ? sh[l] : 0.f;
        float b = (l < 8) ? sh[32 + l] : 0.f;
        a = warpReduceSum(a);
        b = warpReduceSum(b);
        if (l == 0) { sh[0] = a; sh[1] = b; }
    }
    __syncthreads();
    float mean = sh[0] * (1.0f / EDIM);
    float var  = sh[1] * (1.0f / EDIM) - mean * mean;
    float inv  = rsqrtf(var + 1e-5f);
    for (int i = threadIdx.x; i < EDIM; i += 256) {
        yr[i] = (xr[i] - mean) * inv * gamma[i] + beta[i];
    }
}

// ------------------------------ twiddle fill -------------------------------
__global__ void fill_twiddle_kernel(float2* __restrict__ tw)
{
    int k = blockIdx.x * 256 + threadIdx.x;
    if (k < 1024) {
        double ang = -6.283185307179586476925286766559 * (double)k / 2048.0;
        tw[k] = make_float2((float)cos(ang), (float)sin(ang));
    }
}

// ------------------------------ batched column FFT -------------------------
// One block: 4 adjacent real columns (2 packed complex FFTs) of a (2048 x
// EDIM) per-batch matrix.  Output = Re(FFT(col)) * scale.
__global__ __launch_bounds__(256) void fft_cols_kernel(
    const float* __restrict__ in, float* __restrict__ out,
    const float2* __restrict__ tw, float scale)
{
    __shared__ float2 z1[SEQ];
    __shared__ float2 z2[SEQ];
    __shared__ float2 twz[1024];

    const long long bofs = (long long)blockIdx.y * SEQ * EDIM + blockIdx.x * 4;
    const float* src = in + bofs;
    float* dst = out + bofs;
    int tid = threadIdx.x;

    for (int i = tid; i < 1024; i += 256) twz[i] = tw[i];

    for (int r = tid; r < SEQ; r += 256) {
        float4 v = *reinterpret_cast<const float4*>(src + (long long)r * EDIM);
        int br = __brev((unsigned)r) >> 21;   // 11-bit reversal
        z1[br] = make_float2(v.x, v.y);
        z2[br] = make_float2(v.z, v.w);
    }
    __syncthreads();

    for (int s = 0; s < 11; s++) {
        int half = 1 << s;
        for (int b = tid; b < 1024; b += 256) {
            int pos = b & (half - 1);
            int i0 = ((b >> s) << (s + 1)) + pos;
            int i1 = i0 + half;
            float2 w = twz[pos << (10 - s)];
            float2 a, c; float tr, ti;
            a = z1[i0]; c = z1[i1];
            tr = w.x * c.x - w.y * c.y;
            ti = w.x * c.y + w.y * c.x;
            z1[i0] = make_float2(a.x + tr, a.y + ti);
            z1[i1] = make_float2(a.x - tr, a.y - ti);
            a = z2[i0]; c = z2[i1];
            tr = w.x * c.x - w.y * c.y;
            ti = w.x * c.y + w.y * c.x;
            z2[i0] = make_float2(a.x + tr, a.y + ti);
            z2[i1] = make_float2(a.x - tr, a.y - ti);
        }
        __syncthreads();
    }

    // unpack: ReA[k]=(ReZ[k]+ReZ[N-k])/2, ReB[k]=(ImZ[k]+ImZ[N-k])/2
    float h = 0.5f * scale;
    for (int r = tid; r < SEQ; r += 256) {
        int rr = (SEQ - r) & (SEQ - 1);
        float4 o;
        o.x = h * (z1[r].x + z1[rr].x);
        o.y = h * (z1[r].y + z1[rr].y);
        o.z = h * (z2[r].x + z2[rr].x);
        o.w = h * (z2[r].y + z2[rr].y);
        *reinterpret_cast<float4*>(dst + (long long)r * EDIM) = o;
    }
}

// ------------------------------ abs-softmax --------------------------------
__global__ __launch_bounds__(256) void softmax_abs_kernel(float* __restrict__ s)
{
    long long row = blockIdx.x;
    float* sr = s + row * (long long)SEQ;
    float vals[8];
    float mx = -1e30f;
    #pragma unroll
    for (int i = 0; i < 8; i++) {
        float v = fabsf(sr[threadIdx.x + i * 256]);
        vals[i] = v;
        mx = fmaxf(mx, v);
    }
    __shared__ float sh[32];
    mx = warpReduceMax(mx);
    int w = threadIdx.x >> 5, l = threadIdx.x & 31;
    if (l == 0) sh[w] = mx;
    __syncthreads();
    if (w == 0) {
        float a = (l < 8) ? sh[l] : -1e30f;
        a = warpReduceMax(a);
        if (l == 0) sh[0] = a;
    }
    __syncthreads();
    float M = sh[0];
    float sum = 0.f;
    #pragma unroll
    for (int i = 0; i < 8; i++) {
        vals[i] = expf(vals[i] - M);
        sum += vals[i];
    }
    __syncthreads();
    sum = warpReduceSum(sum);
    if (l == 0) sh[w] = sum;
    __syncthreads();
    if (w == 0) {
        float a = (l < 8) ? sh[l] : 0.f;
        a = warpReduceSum(a);
        if (l == 0) sh[0] = a;
    }
    __syncthreads();
    float inv = 1.0f / sh[0];
    #pragma unroll
    for (int i = 0; i < 8; i++) {
        sr[threadIdx.x + i * 256] = vals[i] * inv;
    }
}

// ------------------------------ SGEMM --------------------------------------
// C[M,N] = alpha * A @ op(B) (+ Res); batched via blockIdx.z.
// 128x128 tile, BK=8, 8x8/thread, 256 threads, double-buffered smem.
template <bool TRANSB>
__global__ __launch_bounds__(256) void sgemm_kernel(
    const float* __restrict__ A, int lda, long long sA,
    const float* __restrict__ B, int ldb, long long sB,
    float* __restrict__ C, int ldc, long long sC,
    int M, int N, int K, float alpha,
    const float* __restrict__ Res, long long sRes)
{
    const int BM = 128, BN = 128, BK = 8, TM = 8, TN = 8;
    __shared__ float As[2][BK][BM];
    __shared__ float Bs[2][BK][BN];

    long long bz = blockIdx.z;
    A += bz * sA;
    B += bz * sB;
    C += bz * sC;
    if (Res) Res += bz * sRes;

    int row0 = blockIdx.y * BM;
    int col0 = blockIdx.x * BN;
    int tid = threadIdx.x;
    int tx = tid & 15, ty = tid >> 4;

    // per-thread fixed load coordinates
    int amv[4], akv[4], bnv[4], bkv[4];
    #pragma unroll
    for (int i = 0; i < 4; i++) {
        int idx = tid + i * 256;
        amv[i] = idx >> 3;  akv[i] = idx & 7;       // A tile coords
        if (!TRANSB) { bkv[i] = idx >> 7; bnv[i] = idx & 127; }
        else         { bnv[i] = idx >> 3; bkv[i] = idx & 7;   }
    }

    float ra_g[4], rb_g[4];
    float acc[TM][TN];
    #pragma unroll
    for (int i = 0; i < TM; i++)
        #pragma unroll
        for (int j = 0; j < TN; j++) acc[i][j] = 0.f;

    // prologue load k0 = 0
    #pragma unroll
    for (int i = 0; i < 4; i++) {
        int gr = row0 + amv[i], gk = akv[i];
        ra_g[i] = (gr < M && gk < K) ? A[(long long)gr * lda + gk] : 0.f;
        int gc = col0 + bnv[i], gk2 = bkv[i];
        if (!TRANSB)
            rb_g[i] = (gk2 < K && gc < N) ? B[(long long)gk2 * ldb + gc] : 0.f;
        else
            rb_g[i] = (gk2 < K && gc < N) ? B[(long long)gc * ldb + gk2] : 0.f;
    }
    #pragma unroll
    for (int i = 0; i < 4; i++) {
        As[0][akv[i]][amv[i]] = ra_g[i];
        Bs[0][bkv[i]][bnv[i]] = rb_g[i];
    }
    __syncthreads();

    int buf = 0;
    for (int k0 = 0; k0 < K; k0 += BK) {
        bool has_next = (k0 + BK) < K;
        if (has_next) {
            int kn = k0 + BK;
            #pragma unroll
            for (int i = 0; i < 4; i++) {
                int gr = row0 + amv[i], gk = kn + akv[i];
                ra_g[i] = (gr < M && gk < K) ? A[(long long)gr * lda + gk] : 0.f;
                int gc = col0 + bnv[i], gk2 = kn + bkv[i];
                if (!TRANSB)
                    rb_g[i] = (gk2 < K && gc < N) ? B[(long long)gk2 * ldb + gc] : 0.f;
                else
                    rb_g[i] = (gk2 < K && gc < N) ? B[(long long)gc * ldb + gk2] : 0.f;
            }
        }

        #pragma unroll
        for (int kk = 0; kk < BK; kk++) {
            float4 a0 = *reinterpret_cast<const float4*>(&As[buf][kk][ty * TM]);
            float4 a1 = *reinterpret_cast<const float4*>(&As[buf][kk][ty * TM + 4]);
            float4 b0 = *reinterpret_cast<const float4*>(&Bs[buf][kk][tx * TN]);
            float4 b1 = *reinterpret_cast<const float4*>(&Bs[buf][kk][tx * TN + 4]);
            float ra[8] = {a0.x, a0.y, a0.z, a0.w, a1.x, a1.y, a1.z, a1.w};
            float rb[8] = {b0.x, b0.y, b0.z, b0.w, b1.x, b1.y, b1.z, b1.w};
            #pragma unroll
            for (int i = 0; i < TM; i++)
                #pragma unroll
                for (int j = 0; j < TN; j++)
                    acc[i][j] += ra[i] * rb[j];
        }

        if (has_next) {
            #pragma unroll
            for (int i = 0; i < 4; i++) {
                As[buf ^ 1][akv[i]][amv[i]] = ra_g[i];
                Bs[buf ^ 1][bkv[i]][bnv[i]] = rb_g[i];
            }
        }
        __syncthreads();
        buf ^= 1;
    }

    #pragma unroll
    for (int i = 0; i < TM; i++) {
        int r = row0 + ty * TM + i;
        if (r >= M) continue;
        #pragma unroll
        for (int j = 0; j < TN; j++) {
            int c = col0 + tx * TN + j;
            if (c >= N) continue;
            float v = alpha * acc[i][j];
            if (Res) v += Res[(long long)r * ldc + c];
            C[(long long)r * ldc + c] = v;
        }
    }
}

// ------------------------------ host side ----------------------------------
static inline void run_gemm(bool transb,
                            const float* A, int lda, long long sA,
                            const float* B, int ldb, long long sB,
                            float* C, int ldc, long long sC,
                            int M, int N, int K, float alpha,
                            const float* Res, long long sRes, int nb)
{
    dim3 grid((N + 127) / 128, (M + 127) / 128, nb);
    if (transb)
        sgemm_kernel<true><<<grid, 256>>>(A, lda, sA, B, ldb, sB, C, ldc, sC,
                                          M, N, K, alpha, Res, sRes);
    else
        sgemm_kernel<false><<<grid, 256>>>(A, lda, sA, B, ldb, sB, C, ldc, sC,
                                           M, N, K, alpha, Res, sRes);
}

extern "C" void kernel_launch(void* const* d_in, const int* in_sizes, int n_in,
                              void* d_out, int out_size)
{
    const float* x     = (const float*)d_in[0];  // (4,2048,1280)
    const float* Wqkv  = (const float*)d_in[1];  // (1280,975)
    const float* Wq    = (const float*)d_in[2];  // (325,1280)
    const float* Wk    = (const float*)d_in[3];  // (325,1280)
    const float* Wv    = (const float*)d_in[4];  // (325,1280)
    const float* Wout  = (const float*)d_in[5];  // (1280,1280)
    const float* gamma = (const float*)d_in[6];  // (1280,)
    const float* beta  = (const float*)d_in[7];  // (1280,)
    float* out = (float*)d_out;                  // (4,2048,1280)

    float* buf = nullptr;
    cudaGetSymbolAddress((void**)&buf, g_buf);

    float* xn     = buf + OFF_XNORM;
    float* qkv    = buf + OFF_QKV;
    float* q      = buf + OFF_Q;
    float* k      = buf + OFF_K;
    float* v      = buf + OFF_V;
    float* qf     = buf + OFF_QF;
    float* kf     = buf + OFF_KF;
    float* vf     = buf + OFF_VF;
    float* scores = buf + OFF_SCORES;
    float2* tw    = (float2*)(buf + OFF_TW);

    const long long sT = (long long)SEQ * EDIM;
    const long long sS = (long long)SEQ * SEQ;
    const float scale = 0.07905694150420949f;     // 1/sqrt(160)

    layernorm_kernel<<<BSROWS, 256>>>(x, gamma, beta, xn);
    fill_twiddle_kernel<<<4, 256>>>(tw);

    run_gemm(false, xn, EDIM, 0, Wqkv, N3R, 0, qkv, N3R, 0,
             BSROWS, N3R, EDIM, 1.f, nullptr, 0, 1);

    run_gemm(false, qkv + 0 * RANKD, N3R, 0, Wq, EDIM, 0, q, EDIM, 0,
             BSROWS, EDIM, RANKD, 1.f, nullptr, 0, 1);
    run_gemm(false, qkv + 1 * RANKD, N3R, 0, Wk, EDIM, 0, k, EDIM, 0,
             BSROWS, EDIM, RANKD, 1.f, nullptr, 0, 1);
    run_gemm(false, qkv + 2 * RANKD, N3R, 0, Wv, EDIM, 0, v, EDIM, 0,
             BSROWS, EDIM, RANKD, 1.f, nullptr, 0, 1);

    {
        dim3 g(EDIM / 4, BATCH);
        fft_cols_kernel<<<g, 256>>>(q, qf, tw, 1.0f);
        fft_cols_kernel<<<g, 256>>>(k, kf, tw, 1.0f);
        fft_cols_kernel<<<g, 256>>>(v, vf, tw, 1.0f);
    }

    run_gemm(true, qf, EDIM, sT, kf, EDIM, sT, scores, SEQ, sS,
             SEQ, SEQ, EDIM, scale, nullptr, 0, BATCH);

    softmax_abs_kernel<<<BATCH * SEQ, 256>>>(scores);

    run_gemm(false, scores, SEQ, sS, vf, EDIM, sT, q, EDIM, sT,
             SEQ, EDIM, SEQ, 1.f, nullptr, 0, BATCH);

    {
        dim3 g(EDIM / 4, BATCH);
        fft_cols_kernel<<<g, 256>>>(q, k, tw, 1.0f / 2048.0f);
    }

    run_gemm(false, k, EDIM, 0, Wout, EDIM, 0, out, EDIM, 0,
             BSROWS, EDIM, EDIM, 1.f, x, 0, 1);
}

// round 6
// speedup vs baseline: 4.4335x; 2.3573x over previous
#include <cuda_runtime.h>
#include <cuda_bf16.h>
#include <math.h>
#include <stdint.h>

// ---------------------------------------------------------------------------
// RobustAttentionBlock (B=4, S=2048, E=1280, R=325, 3R=975) — mma.sync version
// (tcgen05 unavailable: harness targets baseline sm_100, not sm_100a)
//
// Re(FFT)/Re(IFFT) via radix-2 smem FFT (cos even => ReIFFT = ReFFT/2048).
// All GEMMs on mma.sync.m16n8k16 bf16 with 2-way split (hi+lo) and fp32
// accumulation: A@B ~= Ah@Bh + Ah@Bl + Al@Bh  (error ~2^-16).
// ---------------------------------------------------------------------------

#define EDIM   1280
#define SEQ    2048
#define BATCH  4
#define RANKD  325
#define RANKP  328          // padded K (zero-filled, 8-multiple)
#define N3R    975
#define BSROWS (BATCH * SEQ)

// ------------------------- fp32 scratch ------------------------------------
#define F_SC   0LL                               // scores / qkv_f temp
#define F_Q    (F_SC + 4LL*2048*2048)
#define F_K    (F_Q + 8192LL*1280)
#define F_V    (F_K + 8192LL*1280)
#define F_TW   (F_V + 8192LL*1280)
#define F_TOT  (F_TW + 2048LL)
__device__ float g_buf[F_TOT];

// ------------------------- bf16 scratch ------------------------------------
#define SZ_T   (8192LL*1280)
#define SZ_SC  (4LL*2048*2048)
#define H_XNH   0LL
#define H_XNL   (H_XNH + SZ_T)
#define H_WQKVH (H_XNL + SZ_T)
#define H_WQKVL (H_WQKVH + 975LL*1280)
#define H_QBH   (H_WQKVL + 975LL*1280)
#define H_QBL   (H_QBH + 8192LL*RANKP)
#define H_KBH   (H_QBL + 8192LL*RANKP)
#define H_KBL   (H_KBH + 8192LL*RANKP)
#define H_VBH   (H_KBL + 8192LL*RANKP)
#define H_VBL   (H_VBH + 8192LL*RANKP)
#define H_WQH   (H_VBL + 8192LL*RANKP)
#define H_WQL   (H_WQH + 1280LL*RANKP)
#define H_WKH   (H_WQL + 1280LL*RANKP)
#define H_WKL   (H_WKH + 1280LL*RANKP)
#define H_WVH   (H_WKL + 1280LL*RANKP)
#define H_WVL   (H_WVH + 1280LL*RANKP)
#define H_QFH   (H_WVL + 1280LL*RANKP)
#define H_QFL   (H_QFH + SZ_T)
#define H_KFH   (H_QFL + SZ_T)
#define H_KFL   (H_KFH + SZ_T)
#define H_VFH   (H_KFL + SZ_T)   // transposed: per batch 1280 x 2048
#define H_VFL   (H_VFH + SZ_T)
#define H_ATH   (H_VFL + SZ_T)
#define H_ATL   (H_ATH + SZ_SC)
#define H_AOH   (H_ATL + SZ_SC)
#define H_AOL   (H_AOH + SZ_T)
#define H_WOH   (H_AOL + SZ_T)
#define H_WOL   (H_WOH + 1280LL*1280)
#define H_TOT   (H_WOL + 1280LL*1280)
__device__ __nv_bfloat16 g_hb[H_TOT];

// ------------------------------ PTX helpers --------------------------------
__device__ __forceinline__ uint32_t smem_u32(const void* p) {
    uint32_t a;
    asm("{ .reg .u64 t; cvta.to.shared.u64 t, %1; cvt.u32.u64 %0, t; }"
        : "=r"(a) : "l"(p));
    return a;
}
__device__ __forceinline__ void cp_async16(uint32_t sa, const void* g, int ssz) {
    asm volatile("cp.async.ca.shared.global [%0], [%1], 16, %2;"
                 :: "r"(sa), "l"(g), "r"(ssz) : "memory");
}
__device__ __forceinline__ void cp_commit() {
    asm volatile("cp.async.commit_group;" ::: "memory");
}
template <int NG>
__device__ __forceinline__ void cp_wait() {
    asm volatile("cp.async.wait_group %0;" :: "n"(NG) : "memory");
}
__device__ __forceinline__ void ldm4(uint32_t* r, uint32_t a) {
    asm volatile("ldmatrix.sync.aligned.m8n8.x4.shared.b16 {%0,%1,%2,%3}, [%4];"
                 : "=r"(r[0]), "=r"(r[1]), "=r"(r[2]), "=r"(r[3]) : "r"(a));
}
__device__ __forceinline__ void ldm2(uint32_t* r, uint32_t a) {
    asm volatile("ldmatrix.sync.aligned.m8n8.x2.shared.b16 {%0,%1}, [%2];"
                 : "=r"(r[0]), "=r"(r[1]) : "r"(a));
}
__device__ __forceinline__ void mma16816(float* c, const uint32_t* a,
                                         const uint32_t* b) {
    asm volatile(
        "mma.sync.aligned.m16n8k16.row.col.f32.bf16.bf16.f32 "
        "{%0,%1,%2,%3}, {%4,%5,%6,%7}, {%8,%9}, {%0,%1,%2,%3};"
        : "+f"(c[0]), "+f"(c[1]), "+f"(c[2]), "+f"(c[3])
        : "r"(a[0]), "r"(a[1]), "r"(a[2]), "r"(a[3]), "r"(b[0]), "r"(b[1]));
}

__device__ __forceinline__ void split_bf(float v, __nv_bfloat16& h, __nv_bfloat16& l) {
    h = __float2bfloat16(v);
    l = __float2bfloat16(v - __bfloat162float(h));
}

// ------------------------------ reductions ---------------------------------
__device__ __forceinline__ float warpReduceSum(float v) {
    #pragma unroll
    for (int o = 16; o > 0; o >>= 1) v += __shfl_xor_sync(0xffffffffu, v, o);
    return v;
}
__device__ __forceinline__ float warpReduceMax(float v) {
    #pragma unroll
    for (int o = 16; o > 0; o >>= 1) v = fmaxf(v, __shfl_xor_sync(0xffffffffu, v, o));
    return v;
}

// ------------------------------ layernorm -> bf16 hi/lo --------------------
__global__ __launch_bounds__(256) void layernorm_kernel(
    const float* __restrict__ x, const float* __restrict__ gamma,
    const float* __restrict__ beta,
    __nv_bfloat16* __restrict__ yh, __nv_bfloat16* __restrict__ yl)
{
    long long row = blockIdx.x;
    const float* xr = x + row * EDIM;

    float s = 0.f, s2 = 0.f;
    for (int i = threadIdx.x; i < EDIM; i += 256) {
        float v = xr[i];
        s += v; s2 += v * v;
    }
    __shared__ float sh[64];
    s  = warpReduceSum(s);
    s2 = warpReduceSum(s2);
    int w = threadIdx.x >> 5, l = threadIdx.x & 31;
    if (l == 0) { sh[w] = s; sh[32 + w] = s2; }
    __syncthreads();
    if (w == 0) {
        float a = (l < 8) ? sh[l] : 0.f;
        float b = (l < 8) ? sh[32 + l] : 0.f;
        a = warpReduceSum(a);
        b = warpReduceSum(b);
        if (l == 0) { sh[0] = a; sh[1] = b; }
    }
    __syncthreads();
    float mean = sh[0] * (1.0f / EDIM);
    float var  = sh[1] * (1.0f / EDIM) - mean * mean;
    float inv  = rsqrtf(var + 1e-5f);
    for (int i = threadIdx.x; i < EDIM; i += 256) {
        float v = (xr[i] - mean) * inv * gamma[i] + beta[i];
        __nv_bfloat16 h, lo; split_bf(v, h, lo);
        yh[row * EDIM + i] = h;
        yl[row * EDIM + i] = lo;
    }
}

// ------------------------------ twiddles -----------------------------------
__global__ void fill_twiddle_kernel(float2* __restrict__ tw)
{
    int k = blockIdx.x * 256 + threadIdx.x;
    if (k < 1024) {
        double ang = -6.283185307179586476925286766559 * (double)k / 2048.0;
        tw[k] = make_float2((float)cos(ang), (float)sin(ang));
    }
}

// ------------------------- transpose + split (weights) ---------------------
__global__ __launch_bounds__(256) void transpose_split_kernel(
    const float* __restrict__ src, int R, int C,
    __nv_bfloat16* __restrict__ dh, __nv_bfloat16* __restrict__ dl, int dld)
{
    __shared__ float t[32][33];
    int c0 = blockIdx.x * 32, r0 = blockIdx.y * 32;
    int tx = threadIdx.x & 31, ty = threadIdx.x >> 5;
    for (int j = ty; j < 32; j += 8) {
        int y = r0 + j, xx = c0 + tx;
        t[j][tx] = (y < R && xx < C) ? src[(long long)y * C + xx] : 0.f;
    }
    __syncthreads();
    for (int j = ty; j < 32; j += 8) {
        int dr = c0 + j;
        int dc = r0 + tx;
        if (dr < C && dc < R) {
            __nv_bfloat16 h, lo; split_bf(t[tx][j], h, lo);
            dh[(long long)dr * dld + dc] = h;
            dl[(long long)dr * dld + dc] = lo;
        }
    }
}

// ------------------------- split qkv_f into q/k/v bufs ---------------------
__global__ __launch_bounds__(256) void split3_kernel(
    const float* __restrict__ qkvf,
    __nv_bfloat16* __restrict__ qh, __nv_bfloat16* __restrict__ ql,
    __nv_bfloat16* __restrict__ kh, __nv_bfloat16* __restrict__ kl,
    __nv_bfloat16* __restrict__ vh, __nv_bfloat16* __restrict__ vl)
{
    int c = blockIdx.x * 256 + threadIdx.x;
    if (c >= N3R) return;
    long long r = blockIdx.y;
    float v = qkvf[r * N3R + c];
    __nv_bfloat16 h, lo; split_bf(v, h, lo);
    int b = (c >= 650) ? 2 : (c >= 325 ? 1 : 0);
    int cc = c - b * 325;
    __nv_bfloat16* dh = (b == 0) ? qh : (b == 1 ? kh : vh);
    __nv_bfloat16* dl = (b == 0) ? ql : (b == 1 ? kl : vl);
    dh[r * RANKP + cc] = h;
    dl[r * RANKP + cc] = lo;
}

// ------------------------------ column FFT ---------------------------------
template <int OMODE>
__global__ __launch_bounds__(256) void fft_cols_kernel(
    const float* __restrict__ in,
    __nv_bfloat16* __restrict__ oh, __nv_bfloat16* __restrict__ ol,
    const float2* __restrict__ tw, float scale)
{
    __shared__ float2 z1[SEQ];
    __shared__ float2 z2[SEQ];
    __shared__ float2 twz[1024];

    int col0 = blockIdx.x * 4;
    long long b = blockIdx.y;
    const float* src = in + b * SEQ * EDIM + col0;
    int tid = threadIdx.x;

    for (int i = tid; i < 1024; i += 256) twz[i] = tw[i];

    for (int r = tid; r < SEQ; r += 256) {
        float4 v = *reinterpret_cast<const float4*>(src + (long long)r * EDIM);
        int br = __brev((unsigned)r) >> 21;
        z1[br] = make_float2(v.x, v.y);
        z2[br] = make_float2(v.z, v.w);
    }
    __syncthreads();

    for (int s = 0; s < 11; s++) {
        int half = 1 << s;
        for (int bb = tid; bb < 1024; bb += 256) {
            int pos = bb & (half - 1);
            int i0 = ((bb >> s) << (s + 1)) + pos;
            int i1 = i0 + half;
            float2 w = twz[pos << (10 - s)];
            float2 a, c; float tr, ti;
            a = z1[i0]; c = z1[i1];
            tr = w.x * c.x - w.y * c.y;
            ti = w.x * c.y + w.y * c.x;
            z1[i0] = make_float2(a.x + tr, a.y + ti);
            z1[i1] = make_float2(a.x - tr, a.y - ti);
            a = z2[i0]; c = z2[i1];
            tr = w.x * c.x - w.y * c.y;
            ti = w.x * c.y + w.y * c.x;
            z2[i0] = make_float2(a.x + tr, a.y + ti);
            z2[i1] = make_float2(a.x - tr, a.y - ti);
        }
        __syncthreads();
    }

    float h = 0.5f * scale;
    for (int r = tid; r < SEQ; r += 256) {
        int rr = (SEQ - r) & (SEQ - 1);
        float o0 = h * (z1[r].x + z1[rr].x);
        float o1 = h * (z1[r].y + z1[rr].y);
        float o2 = h * (z2[r].x + z2[rr].x);
        float o3 = h * (z2[r].y + z2[rr].y);
        __nv_bfloat16 h0,l0,h1,l1,h2,l2,h3,l3;
        split_bf(o0,h0,l0); split_bf(o1,h1,l1);
        split_bf(o2,h2,l2); split_bf(o3,h3,l3);
        if (OMODE == 0) {
            long long off = b * SEQ * EDIM + (long long)r * EDIM + col0;
            oh[off+0]=h0; oh[off+1]=h1; oh[off+2]=h2; oh[off+3]=h3;
            ol[off+0]=l0; ol[off+1]=l1; ol[off+2]=l2; ol[off+3]=l3;
        } else {
            long long ob = b * (long long)EDIM * SEQ;
            oh[ob + (long long)(col0+0)*SEQ + r] = h0;
            oh[ob + (long long)(col0+1)*SEQ + r] = h1;
            oh[ob + (long long)(col0+2)*SEQ + r] = h2;
            oh[ob + (long long)(col0+3)*SEQ + r] = h3;
            ol[ob + (long long)(col0+0)*SEQ + r] = l0;
            ol[ob + (long long)(col0+1)*SEQ + r] = l1;
            ol[ob + (long long)(col0+2)*SEQ + r] = l2;
            ol[ob + (long long)(col0+3)*SEQ + r] = l3;
        }
    }
}

// ------------------------------ abs-softmax -> bf16 hi/lo ------------------
__global__ __launch_bounds__(256) void softmax_abs_kernel(
    const float* __restrict__ s,
    __nv_bfloat16* __restrict__ ah, __nv_bfloat16* __restrict__ al)
{
    long long row = blockIdx.x;
    const float* sr = s + row * (long long)SEQ;
    float vals[8];
    float mx = -1e30f;
    #pragma unroll
    for (int i = 0; i < 8; i++) {
        float v = fabsf(sr[threadIdx.x + i * 256]);
        vals[i] = v;
        mx = fmaxf(mx, v);
    }
    __shared__ float sh[32];
    mx = warpReduceMax(mx);
    int w = threadIdx.x >> 5, l = threadIdx.x & 31;
    if (l == 0) sh[w] = mx;
    __syncthreads();
    if (w == 0) {
        float a = (l < 8) ? sh[l] : -1e30f;
        a = warpReduceMax(a);
        if (l == 0) sh[0] = a;
    }
    __syncthreads();
    float M = sh[0];
    float sum = 0.f;
    #pragma unroll
    for (int i = 0; i < 8; i++) {
        vals[i] = expf(vals[i] - M);
        sum += vals[i];
    }
    __syncthreads();
    sum = warpReduceSum(sum);
    if (l == 0) sh[w] = sum;
    __syncthreads();
    if (w == 0) {
        float a = (l < 8) ? sh[l] : 0.f;
        a = warpReduceSum(a);
        if (l == 0) sh[0] = a;
    }
    __syncthreads();
    float inv = 1.0f / sh[0];
    #pragma unroll
    for (int i = 0; i < 8; i++) {
        float v = vals[i] * inv;
        __nv_bfloat16 h, lo; split_bf(v, h, lo);
        long long off = row * (long long)SEQ + threadIdx.x + i * 256;
        ah[off] = h;
        al[off] = lo;
    }
}

// ------------------------------ HMMA GEMM ----------------------------------
// C[M,N] = alpha * (Ah+Al)[M,K] @ (Bh+Bl)[N,K]^T (+ Res), lo*lo dropped.
// 128x128 CTA tile, BK=32, 8 warps (2x4), warp tile 64x32.
// Smem rows padded to 80B (ldmatrix conflict-free). cp.async double buffer.
#define BKC     32
#define ROWB    80                       // bytes per smem row
#define TILEB   (128 * ROWB)             // 10240
#define STAGEB  (4 * TILEB)              // 40960
#define GEMM_SMEM (2 * STAGEB)           // 81920

__device__ __forceinline__ void load_tile_async(
    uint32_t tb, const __nv_bfloat16* __restrict__ src, long long row0,
    int ld, int nvalid, int kbase, int K, int tid)
{
    #pragma unroll
    for (int j = 0; j < 2; j++) {
        int row = (tid >> 2) + j * 64;
        int c = tid & 3;
        uint32_t sa = tb + row * ROWB + c * 16;
        const __nv_bfloat16* g = src + (row0 + row) * (long long)ld + kbase + c * 8;
        int ssz = (row < nvalid && (kbase + c * 8) < K) ? 16 : 0;
        cp_async16(sa, g, ssz);
    }
}

__global__ void __launch_bounds__(256, 1) hmma_gemm_kernel(
    const __nv_bfloat16* __restrict__ Ah, const __nv_bfloat16* __restrict__ Al,
    int lda, long long sA,
    const __nv_bfloat16* __restrict__ Bh, const __nv_bfloat16* __restrict__ Bl,
    int ldb, long long sB,
    float* __restrict__ C, int ldc, long long sC,
    int M, int N, int K, float alpha,
    const float* __restrict__ Res, long long sRes)
{
    extern __shared__ char smem[];
    uint32_t sb = smem_u32(smem);
    int tid = threadIdx.x;
    int lane = tid & 31, w = tid >> 5;
    int wm = w & 1, wn = w >> 1;

    long long bz = blockIdx.z;
    Ah += bz * sA; Al += bz * sA;
    Bh += bz * sB; Bl += bz * sB;
    C  += bz * sC;
    if (Res) Res += bz * sRes;

    long long m0 = (long long)blockIdx.y * 128;
    int n0 = blockIdx.x * 128;
    int nvB = N - n0; if (nvB > 128) nvB = 128;

    float acc[4][4][4];
    #pragma unroll
    for (int i = 0; i < 4; i++)
        #pragma unroll
        for (int j = 0; j < 4; j++)
            #pragma unroll
            for (int e = 0; e < 4; e++) acc[i][j][e] = 0.f;

    // precomputed ldmatrix intra-tile offsets
    int l16 = lane & 15;
    uint32_t offA = (uint32_t)((wm * 64 + (lane & 15)) * ROWB + ((lane >> 4) & 1) * 16);
    uint32_t offB = (uint32_t)((wn * 32 + (l16 & 7)) * ROWB + ((l16 >> 3) & 1) * 16);

    int nch = (K + BKC - 1) / BKC;

    // prologue: stage 0
    load_tile_async(sb,             Ah, m0, lda, 128, 0, K, tid);
    load_tile_async(sb + TILEB,     Al, m0, lda, 128, 0, K, tid);
    load_tile_async(sb + 2 * TILEB, Bh, n0, ldb, nvB, 0, K, tid);
    load_tile_async(sb + 3 * TILEB, Bl, n0, ldb, nvB, 0, K, tid);
    cp_commit();

    for (int kt = 0; kt < nch; kt++) {
        int st = kt & 1;
        bool has_next = (kt + 1) < nch;
        if (has_next) {
            uint32_t nb = sb + ((kt + 1) & 1) * STAGEB;
            int kb = (kt + 1) * BKC;
            load_tile_async(nb,             Ah, m0, lda, 128, kb, K, tid);
            load_tile_async(nb + TILEB,     Al, m0, lda, 128, kb, K, tid);
            load_tile_async(nb + 2 * TILEB, Bh, n0, ldb, nvB, kb, K, tid);
            load_tile_async(nb + 3 * TILEB, Bl, n0, ldb, nvB, kb, K, tid);
            cp_commit();
            cp_wait<1>();
        } else {
            cp_wait<0>();
        }
        __syncthreads();

        uint32_t tb = sb + st * STAGEB;
        #pragma unroll
        for (int ks = 0; ks < 2; ks++) {
            uint32_t kf = (uint32_t)(ks * 32);
            uint32_t arH[4][4], arL[4][4], brH[4][2], brL[4][2];
            #pragma unroll
            for (int mi = 0; mi < 4; mi++) {
                uint32_t a = tb + offA + (uint32_t)(mi * 16 * ROWB) + kf;
                ldm4(arH[mi], a);
                ldm4(arL[mi], a + TILEB);
            }
            #pragma unroll
            for (int ni = 0; ni < 4; ni++) {
                uint32_t a = tb + 2 * TILEB + offB + (uint32_t)(ni * 8 * ROWB) + kf;
                ldm2(brH[ni], a);
                ldm2(brL[ni], a + TILEB);
            }
            #pragma unroll
            for (int mi = 0; mi < 4; mi++)
                #pragma unroll
                for (int ni = 0; ni < 4; ni++) {
                    mma16816(acc[mi][ni], arH[mi], brH[ni]);
                    mma16816(acc[mi][ni], arH[mi], brL[ni]);
                    mma16816(acc[mi][ni], arL[mi], brH[ni]);
                }
        }
        __syncthreads();
    }

    // epilogue: registers -> gmem
    #pragma unroll
    for (int mi = 0; mi < 4; mi++) {
        long long r0 = m0 + wm * 64 + mi * 16 + (lane >> 2);
        #pragma unroll
        for (int ni = 0; ni < 4; ni++) {
            int col = n0 + wn * 32 + ni * 8 + (lane & 3) * 2;
            float* a = acc[mi][ni];
            if (col < N) {
                long long o0 = r0 * (long long)ldc + col;
                long long o1 = (r0 + 8) * (long long)ldc + col;
                float v0 = alpha * a[0], v2 = alpha * a[2];
                if (Res) { v0 += Res[o0]; v2 += Res[o1]; }
                C[o0] = v0; C[o1] = v2;
                if (col + 1 < N) {
                    float v1 = alpha * a[1], v3 = alpha * a[3];
                    if (Res) { v1 += Res[o0 + 1]; v3 += Res[o1 + 1]; }
                    C[o0 + 1] = v1; C[o1 + 1] = v3;
                }
            }
        }
    }
}

// ------------------------------ host side ----------------------------------
static inline void run_mma(const __nv_bfloat16* Ah, const __nv_bfloat16* Al,
                           int lda, long long sA,
                           const __nv_bfloat16* Bh, const __nv_bfloat16* Bl,
                           int ldb, long long sB,
                           float* C, int ldc, long long sC,
                           int M, int N, int K, float alpha,
                           const float* Res, long long sRes, int nb)
{
    dim3 grid((N + 127) / 128, (M + 127) / 128, nb);
    hmma_gemm_kernel<<<grid, 256, GEMM_SMEM>>>(Ah, Al, lda, sA, Bh, Bl, ldb, sB,
                                               C, ldc, sC, M, N, K, alpha,
                                               Res, sRes);
}

extern "C" void kernel_launch(void* const* d_in, const int* in_sizes, int n_in,
                              void* d_out, int out_size)
{
    const float* x     = (const float*)d_in[0];  // (4,2048,1280)
    const float* Wqkv  = (const float*)d_in[1];  // (1280,975)
    const float* Wq    = (const float*)d_in[2];  // (325,1280)
    const float* Wk    = (const float*)d_in[3];  // (325,1280)
    const float* Wv    = (const float*)d_in[4];  // (325,1280)
    const float* Wout  = (const float*)d_in[5];  // (1280,1280)
    const float* gamma = (const float*)d_in[6];
    const float* beta  = (const float*)d_in[7];
    float* out = (float*)d_out;                  // (4,2048,1280)

    static int smem_set = 0;
    if (!smem_set) {
        cudaFuncSetAttribute(hmma_gemm_kernel,
                             cudaFuncAttributeMaxDynamicSharedMemorySize,
                             GEMM_SMEM);
        smem_set = 1;
    }

    float* fb = nullptr;
    __nv_bfloat16* hb = nullptr;
    cudaGetSymbolAddress((void**)&fb, g_buf);
    cudaGetSymbolAddress((void**)&hb, g_hb);

    float*  scores = fb + F_SC;       // also qkv_f temp
    float*  q      = fb + F_Q;        // also out_fft
    float*  k      = fb + F_K;
    float*  v      = fb + F_V;
    float2* tw     = (float2*)(fb + F_TW);

    const long long sT = (long long)SEQ * EDIM;
    const long long sS = (long long)SEQ * SEQ;
    const float scale = 0.07905694150420949f;   // 1/sqrt(160)

    // 1. LayerNorm -> xn hi/lo; twiddles; weight transposes+splits
    layernorm_kernel<<<BSROWS, 256>>>(x, gamma, beta, hb + H_XNH, hb + H_XNL);
    fill_twiddle_kernel<<<4, 256>>>(tw);
    {
        dim3 b(256);
        transpose_split_kernel<<<dim3((975 + 31) / 32, (1280 + 31) / 32), b>>>(
            Wqkv, 1280, 975, hb + H_WQKVH, hb + H_WQKVL, 1280);
        transpose_split_kernel<<<dim3((1280 + 31) / 32, (325 + 31) / 32), b>>>(
            Wq, 325, 1280, hb + H_WQH, hb + H_WQL, RANKP);
        transpose_split_kernel<<<dim3((1280 + 31) / 32, (325 + 31) / 32), b>>>(
            Wk, 325, 1280, hb + H_WKH, hb + H_WKL, RANKP);
        transpose_split_kernel<<<dim3((1280 + 31) / 32, (325 + 31) / 32), b>>>(
            Wv, 325, 1280, hb + H_WVH, hb + H_WVL, RANKP);
        transpose_split_kernel<<<dim3(40, 40), b>>>(
            Wout, 1280, 1280, hb + H_WOH, hb + H_WOL, 1280);
    }

    // 2. qkv_f = xn @ Wqkv  (8192 x 975, K=1280)
    run_mma(hb + H_XNH, hb + H_XNL, EDIM, 0,
            hb + H_WQKVH, hb + H_WQKVL, EDIM, 0,
            scores, N3R, 0, BSROWS, N3R, EDIM, 1.f, nullptr, 0, 1);

    // 3. split qkv_f into q/k/v bf16 hi/lo (padded ld 328, pad stays zero)
    split3_kernel<<<dim3((N3R + 255) / 256, BSROWS), 256>>>(
        scores, hb + H_QBH, hb + H_QBL, hb + H_KBH, hb + H_KBL,
        hb + H_VBH, hb + H_VBL);

    // 4. q/k/v = qkv_slice @ W  (8192 x 1280, K=328 incl. zero pad)
    run_mma(hb + H_QBH, hb + H_QBL, RANKP, 0, hb + H_WQH, hb + H_WQL, RANKP, 0,
            q, EDIM, 0, BSROWS, EDIM, RANKP, 1.f, nullptr, 0, 1);
    run_mma(hb + H_KBH, hb + H_KBL, RANKP, 0, hb + H_WKH, hb + H_WKL, RANKP, 0,
            k, EDIM, 0, BSROWS, EDIM, RANKP, 1.f, nullptr, 0, 1);
    run_mma(hb + H_VBH, hb + H_VBL, RANKP, 0, hb + H_WVH, hb + H_WVL, RANKP, 0,
            v, EDIM, 0, BSROWS, EDIM, RANKP, 1.f, nullptr, 0, 1);

    // 5. FFT: qf/kf (row layout), vf (transposed for B of attn@V)
    {
        dim3 g(EDIM / 4, BATCH);
        fft_cols_kernel<0><<<g, 256>>>(q, hb + H_QFH, hb + H_QFL, tw, 1.0f);
        fft_cols_kernel<0><<<g, 256>>>(k, hb + H_KFH, hb + H_KFL, tw, 1.0f);
        fft_cols_kernel<1><<<g, 256>>>(v, hb + H_VFH, hb + H_VFL, tw, 1.0f);
    }

    // 6. scores = (qf @ kf^T) / sqrt(160)
    run_mma(hb + H_QFH, hb + H_QFL, EDIM, sT,
            hb + H_KFH, hb + H_KFL, EDIM, sT,
            scores, SEQ, sS, SEQ, SEQ, EDIM, scale, nullptr, 0, BATCH);

    // 7. attn = softmax(|scores|) -> bf16 hi/lo
    softmax_abs_kernel<<<BATCH * SEQ, 256>>>(scores, hb + H_ATH, hb + H_ATL);

    // 8. out_fft = attn @ vf  (B = vfT: 1280 x 2048 per batch) -> q scratch
    run_mma(hb + H_ATH, hb + H_ATL, SEQ, sS,
            hb + H_VFH, hb + H_VFL, SEQ, (long long)EDIM * SEQ,
            q, EDIM, sT, SEQ, EDIM, SEQ, 1.f, nullptr, 0, BATCH);

    // 9. attn_out = Re(FFT(out_fft))/2048 -> bf16 hi/lo
    {
        dim3 g(EDIM / 4, BATCH);
        fft_cols_kernel<0><<<g, 256>>>(q, hb + H_AOH, hb + H_AOL, tw,
                                       1.0f / 2048.0f);
    }

    // 10. out = x + attn_out @ W_out
    run_mma(hb + H_AOH, hb + H_AOL, EDIM, 0, hb + H_WOH, hb + H_WOL, EDIM, 0,
            out, EDIM, 0, BSROWS, EDIM, EDIM, 1.f, x, 0, 1);
}